// round 13
// baseline (speedup 1.0000x reference)
#include <cuda_runtime.h>
#include <cstdint>

#define BB 16384
#define KK 64
#define NA 16

#define N_CTAS 148
#define N_TILES 4096             // 16384 b / 4 b-per-tile
#define TILE_BYTES 36864u        // 256 blocks * 36 floats * 4 (4 b x 64 k)
#define TABLE_BYTES 147456u      // 1024 matrices * 144 B
#define DYN_SMEM (TABLE_BYTES + 2u * TILE_BYTES)   // 221184

// Rotation table in global: R[action][k][6][6] (144 KB), 128B-aligned.
__device__ __align__(128) float d_R[NA * KK * 36];
__device__ unsigned g_done = 0;   // expm producer counter (0..32)
__device__ unsigned g_fin  = 0;   // retirement counter (reset for replay)

static __device__ __forceinline__ uint32_t smem_u32(const void* p) {
    uint32_t a;
    asm("{ .reg .u64 t; cvta.to.shared.u64 t, %1; cvt.u32.u64 %0, t; }"
        : "=r"(a) : "l"(p));
    return a;
}

static __device__ __forceinline__ void mbar_wait(uint32_t bar_a, uint32_t par) {
    uint32_t done;
    asm volatile(
        "{\n\t.reg .pred p;\n\t"
        "mbarrier.try_wait.parity.acquire.cta.shared::cta.b64 p, [%1], %2;\n\t"
        "selp.b32 %0, 1, 0, p;\n\t}"
        : "=r"(done) : "r"(bar_a), "r"(par) : "memory");
    if (!done) {
        asm volatile(
            "{\n\t.reg .pred P1;\n\t"
            "WL_%=:\n\t"
            "mbarrier.try_wait.parity.acquire.cta.shared::cta.b64 P1, [%0], %1, 0x989680;\n\t"
            "@P1 bra.uni WD_%=;\n\t"
            "bra.uni WL_%=;\n\t"
            "WD_%=:\n\t}"
            :: "r"(bar_a), "r"(par) : "memory");
    }
}

static __device__ __forceinline__ void tma_load(uint32_t dst, const void* src,
                                                uint32_t bytes, uint32_t bar) {
    asm volatile(
        "cp.async.bulk.shared::cta.global.mbarrier::complete_tx::bytes "
        "[%0], [%1], %2, [%3];"
        :: "r"(dst), "l"(src), "r"(bytes), "r"(bar) : "memory");
}

// ---------------------------------------------------------------------------
// Single persistent kernel. 148 CTAs x 256 threads (one full wave).
//  - t0: immediately issue TMA loads of tiles j=0,1 (no R dependency).
//  - CTAs 0..31 (threads 0..191): column-parallel expm of the 1024 distinct
//    6x6 matrices into d_R (R11's proven code), then release g_done.
//  - All CTAs: poll g_done==32 (148 pollers only), TMA-stage the FULL 144KB
//    table into smem once, then loop over ~27 tiles with a double-buffered
//    load -> compute -> bulk-store pipeline.
// ---------------------------------------------------------------------------
__global__ void __launch_bounds__(256, 1) fused_kernel(
    const float* __restrict__ gf,
    const int* __restrict__ act,
    const float* __restrict__ act_params,
    const float* __restrict__ basis,
    float* __restrict__ out) {
    extern __shared__ __align__(128) float dyn[];
    __shared__ __align__(8) unsigned long long mbar[3];  // full0, full1, table
    __shared__ float sT[32 * 36];                        // expm squaring scratch

    float* sTable = dyn;                                 // 147456 B
    float* sBuf0 = dyn + TABLE_BYTES / 4;                // 36864 B
    float* sBuf1 = sBuf0 + TILE_BYTES / 4;               // 36864 B

    const int t = threadIdx.x;
    const int cta = blockIdx.x;
    const uint32_t tab_a = smem_u32(sTable);
    const uint32_t b0_a = smem_u32(sBuf0);
    const uint32_t b1_a = smem_u32(sBuf1);
    const uint32_t fbar[2] = { smem_u32(&mbar[0]), smem_u32(&mbar[1]) };
    const uint32_t tbar = smem_u32(&mbar[2]);

    if (t == 0) {
        asm volatile("mbarrier.init.shared.b64 [%0], 1;" :: "r"(fbar[0]) : "memory");
        asm volatile("mbarrier.init.shared.b64 [%0], 1;" :: "r"(fbar[1]) : "memory");
        asm volatile("mbarrier.init.shared.b64 [%0], 1;" :: "r"(tbar) : "memory");
    }
    __syncthreads();

    const int cnt = (N_TILES - cta + N_CTAS - 1) / N_CTAS;   // 27 or 28

    // Prologue: issue loads for tiles j=0 and j=1 right away.
    if (t == 0) {
        const char* gsrc = reinterpret_cast<const char*>(gf);
        asm volatile("mbarrier.arrive.expect_tx.shared.b64 _, [%0], %1;"
                     :: "r"(fbar[0]), "r"(TILE_BYTES) : "memory");
        tma_load(b0_a, gsrc + (size_t)cta * TILE_BYTES, TILE_BYTES, fbar[0]);
        asm volatile("mbarrier.arrive.expect_tx.shared.b64 _, [%0], %1;"
                     :: "r"(fbar[1]), "r"(TILE_BYTES) : "memory");
        tma_load(b1_a, gsrc + (size_t)(cta + N_CTAS) * TILE_BYTES, TILE_BYTES,
                 fbar[1]);
    }

    // Producer CTAs: column-parallel expm while gf streams chip-wide.
    if (cta < 32) {
        const bool worker = (t < 192);
        int s = 0;
        float v[6];
        float A[36];
        int lm = 0, c = 0;
        if (worker) {
            lm = t / 6;                          // local matrix 0..31
            c = t - lm * 6;                      // column 0..5
            const int mat = cta * 32 + lm;
            const int action = mat >> 6;
            const int k = mat & 63;

            float a = act_params[action * KK + k];
            const float* L = basis + k * 36;
#pragma unroll
            for (int i = 0; i < 6; i++)
#pragma unroll
                for (int j = 0; j < 6; j++)
                    A[i * 6 + j] = a * (L[i * 6 + j] - L[j * 6 + i]);

            float nrm = 0.f;
#pragma unroll
            for (int i = 0; i < 6; i++) {
                float rs = 0.f;
#pragma unroll
                for (int j = 0; j < 6; j++) rs += fabsf(A[i * 6 + j]);
                nrm = fmaxf(nrm, rs);
            }
            while (nrm > 0.5f && s < 40) { nrm *= 0.5f; s++; }
            float sc = ldexpf(1.0f, -s);
#pragma unroll
            for (int i = 0; i < 36; i++) A[i] *= sc;

#pragma unroll
            for (int i = 0; i < 6; i++) v[i] = (i == c) ? 1.f : 0.f;
#pragma unroll
            for (int p = 10; p >= 1; --p) {
                float w[6];
                float inv = 1.0f / (float)p;
#pragma unroll
                for (int i = 0; i < 6; i++) {
                    float acc = 0.f;
#pragma unroll
                    for (int j = 0; j < 6; j++)
                        acc = fmaf(A[i * 6 + j], v[j], acc);
                    w[i] = acc * inv + ((i == c) ? 1.f : 0.f);
                }
#pragma unroll
                for (int i = 0; i < 6; i++) v[i] = w[i];
            }
        }
        // Squaring (rare; whole CTA participates in the barriers)
        for (int q = 0; ; q++) {
            bool active = worker && (q < s);
            if (!__syncthreads_or(active)) break;
            if (active) {
#pragma unroll
                for (int i = 0; i < 6; i++) sT[lm * 36 + i * 6 + c] = v[i];
            }
            __syncthreads();
            if (active) {
                float w[6];
#pragma unroll
                for (int i = 0; i < 6; i++) {
                    float acc = 0.f;
#pragma unroll
                    for (int j = 0; j < 6; j++)
                        acc = fmaf(sT[lm * 36 + i * 6 + j], v[j], acc);
                    w[i] = acc;
                }
#pragma unroll
                for (int i = 0; i < 6; i++) v[i] = w[i];
            }
        }
        if (worker) {
            const int mat = cta * 32 + lm;
#pragma unroll
            for (int i = 0; i < 6; i++)
                d_R[mat * 36 + i * 6 + c] = v[i];
        }
        __syncthreads();
        if (t == 0) {
            __threadfence();
            asm volatile("fence.proxy.async;" ::: "memory");
            asm volatile("red.release.gpu.global.add.u32 [%0], 1;"
                         :: "l"(&g_done) : "memory");
        }
    }

    // Stage the full R table once (after the 32 producers are done).
    if (t == 0) {
        unsigned vflag;
        do {
            asm volatile("ld.acquire.gpu.global.u32 %0, [%1];"
                         : "=r"(vflag) : "l"(&g_done) : "memory");
            if (vflag >= 32u) break;
            asm volatile("nanosleep.u32 128;");
        } while (true);
        asm volatile("fence.proxy.async;" ::: "memory");

        asm volatile("mbarrier.arrive.expect_tx.shared.b64 _, [%0], %1;"
                     :: "r"(tbar), "r"(TABLE_BYTES) : "memory");
        const char* rb = reinterpret_cast<const char*>(d_R);
#pragma unroll
        for (int cchunk = 0; cchunk < 4; cchunk++)
            tma_load(tab_a + cchunk * TILE_BYTES, rb + cchunk * TILE_BYTES,
                     TILE_BYTES, tbar);
    }
    mbar_wait(tbar, 0);

    // Steady-state pipeline over this CTA's tiles.
    const int kk36 = (t & 63) * 36;
    const int bl = t >> 6;
    uint32_t pb[2] = { 0u, 0u };

    for (int j = 0; j < cnt; j++) {
        const int buf = j & 1;
        float* bufp = buf ? sBuf1 : sBuf0;
        const uint32_t buf_a = buf ? b1_a : b0_a;
        const int tile = cta + j * N_CTAS;

        const int ab = __ldg(act + tile * 4 + bl);

        mbar_wait(fbar[buf], pb[buf]);
        pb[buf] ^= 1u;

        // Compute: conflict-free LDS.128 (144B stride; 2304-float action
        // stride == 0 mod 32 banks, pattern unchanged).
        float G[36];
        const float4* myG = reinterpret_cast<const float4*>(bufp + t * 36);
#pragma unroll
        for (int q = 0; q < 9; q++) {
            float4 vv = myG[q];
            G[4 * q + 0] = vv.x; G[4 * q + 1] = vv.y;
            G[4 * q + 2] = vv.z; G[4 * q + 3] = vv.w;
        }
        const float4* myR = reinterpret_cast<const float4*>(
            sTable + (size_t)ab * 2304 + kk36);
        float4* myO = reinterpret_cast<float4*>(bufp + t * 36);
#pragma unroll
        for (int rp = 0; rp < 3; rp++) {
            float r[12];
#pragma unroll
            for (int q = 0; q < 3; q++) {
                float4 vv = myR[rp * 3 + q];
                r[4 * q + 0] = vv.x; r[4 * q + 1] = vv.y;
                r[4 * q + 2] = vv.z; r[4 * q + 3] = vv.w;
            }
            float p[12];
#pragma unroll
            for (int l = 0; l < 6; l++) {
                float acc0 = 0.f, acc1 = 0.f;
#pragma unroll
                for (int jj = 0; jj < 6; jj++) {
                    acc0 = fmaf(r[jj],     G[jj * 6 + l], acc0);
                    acc1 = fmaf(r[6 + jj], G[jj * 6 + l], acc1);
                }
                p[l] = acc0; p[6 + l] = acc1;
            }
#pragma unroll
            for (int q = 0; q < 3; q++) {
                float4 vv;
                vv.x = p[4 * q + 0]; vv.y = p[4 * q + 1];
                vv.z = p[4 * q + 2]; vv.w = p[4 * q + 3];
                myO[rp * 3 + q] = vv;
            }
        }

        asm volatile("fence.proxy.async.shared::cta;" ::: "memory");
        __syncthreads();

        if (t == 0) {
            char* gdst = reinterpret_cast<char*>(out) + (size_t)tile * TILE_BYTES;
            asm volatile(
                "cp.async.bulk.global.shared::cta.bulk_group [%0], [%1], %2;"
                :: "l"(gdst), "r"(buf_a), "r"(TILE_BYTES) : "memory");
            asm volatile("cp.async.bulk.commit_group;" ::: "memory");
            if (j + 2 < cnt) {
                // Free this buffer (its store included) before reloading.
                asm volatile("cp.async.bulk.wait_group 0;" ::: "memory");
                asm volatile("mbarrier.arrive.expect_tx.shared.b64 _, [%0], %1;"
                             :: "r"(fbar[buf]), "r"(TILE_BYTES) : "memory");
                tma_load(buf_a,
                         reinterpret_cast<const char*>(gf) +
                             (size_t)(tile + 2 * N_CTAS) * TILE_BYTES,
                         TILE_BYTES, fbar[buf]);
            }
        }
    }

    // Drain outstanding stores before smem is released; reset replay flags.
    if (t == 0) {
        asm volatile("cp.async.bulk.wait_group 0;" ::: "memory");
        unsigned old = atomicAdd(&g_fin, 1u);
        if (old == N_CTAS - 1u) {
            atomicExch(&g_done, 0u);
            atomicExch(&g_fin, 0u);
        }
    }
}

// ---------------------------------------------------------------------------
// Inputs (metadata order): group_feats f32 [B,K*36], act i32 [B],
// act_params f32 [16,K], lie_alg_basis f32 [K,6,6]. Output f32 [B,K*36].
// ---------------------------------------------------------------------------
extern "C" void kernel_launch(void* const* d_in, const int* in_sizes, int n_in,
                              void* d_out, int out_size) {
    const float* gf         = (const float*)d_in[0];
    const int*   act        = (const int*)d_in[1];
    const float* act_params = (const float*)d_in[2];
    const float* basis      = (const float*)d_in[3];
    float* out = (float*)d_out;

    cudaFuncSetAttribute(fused_kernel,
                         cudaFuncAttributeMaxDynamicSharedMemorySize, DYN_SMEM);
    fused_kernel<<<N_CTAS, 256, DYN_SMEM>>>(gf, act, act_params, basis, out);
}